// round 17
// baseline (speedup 1.0000x reference)
#include <cuda_runtime.h>
#include <cuda_bf16.h>
#include <cstdint>

// Problem constants (Wisard_68401649156855)
#define ENTRY_SIZE 1024
#define N_CLASSES  10
#define TUPLE_SIZE 16
#define N_RAMS     64
#define N_ADDR     65536
#define BATCH      8192
#define WORDS_PER_ROW 32
#define N_GROUPS   (BATCH / 32)     // 256 groups of 32 samples

// Scratch: bitsT[w][b]: bit k = samples[b][w*32+k]
__device__ unsigned g_bitsT[WORDS_PER_ROW * BATCH];
// Scratch: bitsE[grp][e]: bit k = samples[grp*32+k][e]  (entry-major)
__device__ unsigned g_bitsE[N_GROUPS * ENTRY_SIZE];

// ---------------------------------------------------------------------------
// Kernel 0: zero the output (harness poisons it; atomics need 0 base).
// ---------------------------------------------------------------------------
__global__ void __launch_bounds__(256) wisard_zero_kernel(float* __restrict__ out)
{
    int i = blockIdx.x * 256 + threadIdx.x;
    if (i < BATCH * N_CLASSES) out[i] = 0.f;
}

// ---------------------------------------------------------------------------
// Kernel 1: pack samples (int32 0/1) -> bit matrix. (unchanged, known correct)
// ---------------------------------------------------------------------------
__global__ void __launch_bounds__(256) wisard_pack_kernel(const int* __restrict__ samples)
{
    int gtid   = blockIdx.x * blockDim.x + threadIdx.x;
    int b      = gtid >> 5;            // warp = sample row
    int lane   = gtid & 31;

    const int4* base = (const int4*)(samples + (size_t)b * ENTRY_SIZE) + lane;
    int4 v[8];
    #pragma unroll
    for (int it = 0; it < 8; ++it)
        v[it] = base[it * 32];

    unsigned j   = lane >> 3;
    unsigned sh  = 4u * (lane & 7);

    #pragma unroll
    for (int it = 0; it < 8; ++it) {
        unsigned nib = (unsigned)(v[it].x != 0)
                     | ((unsigned)(v[it].y != 0) << 1)
                     | ((unsigned)(v[it].z != 0) << 2)
                     | ((unsigned)(v[it].w != 0) << 3);
        unsigned x = nib << sh;
        x |= __shfl_xor_sync(0xffffffffu, x, 1);
        x |= __shfl_xor_sync(0xffffffffu, x, 2);
        x |= __shfl_xor_sync(0xffffffffu, x, 4);
        if ((lane & 7) == 0)
            g_bitsT[(it * 4 + j) * BATCH + b] = x;
    }
}

// ---------------------------------------------------------------------------
// 32x32 bit-matrix transpose across a warp (block-swap butterfly).
// out lane j, bit k  =  in lane k, bit j.
// ---------------------------------------------------------------------------
__device__ __forceinline__ unsigned warp_bit_transpose(unsigned x, int lane)
{
    const unsigned masks[5] = { 0x0000FFFFu, 0x00FF00FFu, 0x0F0F0F0Fu,
                                0x33333333u, 0x55555555u };
    const int shifts[5] = { 16, 8, 4, 2, 1 };
    #pragma unroll
    for (int i = 0; i < 5; ++i) {
        int s = shifts[i];
        unsigned lm = masks[i];
        unsigned y = __shfl_xor_sync(0xffffffffu, x, s);
        if ((lane & s) == 0)
            x = (x & lm) | ((y & lm) << s);
        else
            x = (x & ~lm) | ((y & ~lm) >> s);
    }
    return x;
}

// ---------------------------------------------------------------------------
// Kernel 2: one-time transpose bitsT -> bitsE (entry-major sample words).
// ---------------------------------------------------------------------------
__global__ void __launch_bounds__(256) wisard_transposeE_kernel()
{
    int warpId = (blockIdx.x * 256 + threadIdx.x) >> 5;
    int lane   = threadIdx.x & 31;
    int grp    = warpId >> 5;          // 0..255
    int w      = warpId & 31;          // 0..31

    unsigned x = g_bitsT[w * BATCH + grp * 32 + lane];
    x = warp_bit_transpose(x, lane);
    g_bitsE[grp * ENTRY_SIZE + w * 32 + lane] = x;
}

// ---------------------------------------------------------------------------
// Kernel 3: main WiSARD lookup — CLASS LOOP INSIDE the block for L2 reuse.
// Grid: (256 groups, 2 RAM-halves) = 512 blocks. Block: 256 threads = 8 warps.
// Block (grp, rh) handles 32 samples x RAMs [rh*32, rh*32+32), looping c=0..9.
// At any instant the whole GPU works on ~1-2 classes -> that class's 16 MB
// table slice is L2-resident -> the 4x per-sector reuse materializes.
// Warp wid owns RAMs rh*32 + wid*4 .. +3 (two transpose-pairs per class).
// acc[10] kept in registers; single epilogue reduction; atomicAdd combines
// the two rh contributions (2-term float add is order-independent).
// ---------------------------------------------------------------------------
__global__ void __launch_bounds__(256, 4) wisard_main_kernel(
    const int*   __restrict__ tuple_mapping,  // [N_CLASSES][ENTRY_SIZE]
    const float* __restrict__ ram_table,      // [N_CLASSES][N_RAMS][N_ADDR]
    float*       __restrict__ out)            // [BATCH][N_CLASSES]
{
    const int grp  = blockIdx.x;               // 0..255
    const int rh   = blockIdx.y;               // 0..1
    const int tid  = threadIdx.x;
    const int wid  = tid >> 5;
    const int lane = tid & 31;

    __shared__ __align__(16) unsigned bitS_s[ENTRY_SIZE];        // 4 KB
    __shared__ float                  red[N_CLASSES][8][32];     // 10 KB

    // Prologue: coalesced int4 copy of this group's entry-major words.
    {
        const int4* src = (const int4*)(g_bitsE + grp * ENTRY_SIZE);
        int4*       dst = (int4*)bitS_s;
        dst[tid] = src[tid];                   // 256 * 16B = 4 KB
    }
    __syncthreads();

    const int rbase  = rh * 32 + wid * 4;      // this warp's 4 RAMs
    const int tm_off = (lane >> 4) * 16 + 15 - (lane & 15);

    float acc[N_CLASSES];

    #pragma unroll
    for (int c = 0; c < N_CLASSES; ++c) {
        const int* tmc = tuple_mapping + c * ENTRY_SIZE;
        // Two pair-transposes -> 4 addresses (RAMs rbase..rbase+3)
        int idx0 = tmc[(rbase + 0) * 16 + tm_off];
        int idx1 = tmc[(rbase + 2) * 16 + tm_off];
        unsigned aw0 = warp_bit_transpose(bitS_s[idx0], lane);
        unsigned aw1 = warp_bit_transpose(bitS_s[idx1], lane);

        const float* base = ram_table
            + (size_t)c * (N_RAMS * N_ADDR) + ((size_t)rbase << TUPLE_SIZE);
        float v0 = __ldg(base + (aw0 & 0xFFFFu));
        float v1 = __ldg(base + N_ADDR + (aw0 >> 16));
        float v2 = __ldg(base + 2 * N_ADDR + (aw1 & 0xFFFFu));
        float v3 = __ldg(base + 3 * N_ADDR + (aw1 >> 16));
        acc[c] = (v0 + v1) + (v2 + v3);
    }

    // Epilogue: reduce 8 warps per class, atomicAdd the rh-half contribution.
    #pragma unroll
    for (int c = 0; c < N_CLASSES; ++c)
        red[c][wid][lane] = acc[c];
    __syncthreads();

    #pragma unroll
    for (int c = wid; c < N_CLASSES; c += 8) {
        float s = red[c][0][lane];
        #pragma unroll
        for (int w = 1; w < 8; ++w) s += red[c][w][lane];
        atomicAdd(&out[(grp * 32 + lane) * N_CLASSES + c], s);
    }
}

// ---------------------------------------------------------------------------
// Launch
// ---------------------------------------------------------------------------
extern "C" void kernel_launch(void* const* d_in, const int* in_sizes, int n_in,
                              void* d_out, int out_size)
{
    const int*   samples       = (const int*)  d_in[0];  // [8192][1024] int32
    const int*   tuple_mapping = (const int*)  d_in[1];  // [10][1024]   int32
    const float* ram_table     = (const float*)d_in[2];  // [10][64][65536] float32
    float*       out           = (float*)d_out;          // [8192][10]   float32

    wisard_zero_kernel<<<(BATCH * N_CLASSES + 255) / 256, 256>>>(out);
    wisard_pack_kernel<<<(BATCH * 32) / 256, 256>>>(samples);
    wisard_transposeE_kernel<<<(N_GROUPS * 32 * 32) / 256, 256>>>();

    dim3 grid(N_GROUPS, 2);            // 256 x 2 = 512 blocks
    wisard_main_kernel<<<grid, 256>>>(tuple_mapping, ram_table, out);
}